// round 1
// baseline (speedup 1.0000x reference)
#include <cuda_runtime.h>

#define NNODES 50000
#define NEDGES 1600000

// ---------------- scratch (no allocations allowed) ----------------
__device__ float g_u [NNODES * 128];
__device__ float g_s [NNODES * 128];
__device__ float g_h1[NNODES * 128];
__device__ float g_h2[NNODES * 128];
__device__ float g_p [NNODES * 128];
__device__ float g_q [NNODES * 128];
__device__ int   g_cnt[NNODES];
__device__ float g_inv[NNODES];

// ---------------- packed f32x2 helpers ----------------
__device__ __forceinline__ unsigned long long fma2(unsigned long long a,
                                                   unsigned long long b,
                                                   unsigned long long c) {
    unsigned long long d;
    asm("fma.rn.f32x2 %0, %1, %2, %3;" : "=l"(d) : "l"(a), "l"(b), "l"(c));
    return d;
}
__device__ __forceinline__ unsigned long long pack2(float x, float y) {
    unsigned long long d;
    asm("mov.b64 %0, {%1, %2};" : "=l"(d) : "f"(x), "f"(y));
    return d;
}
__device__ __forceinline__ float2 unpack2(unsigned long long v) {
    float2 r;
    asm("mov.b64 {%0, %1}, %2;" : "=f"(r.x), "=f"(r.y) : "l"(v));
    return r;
}

// ---------------- tiny utility kernels ----------------
__global__ void k_zero_f4(float* __restrict__ ptr) {
    int i = blockIdx.x * blockDim.x + threadIdx.x;          // exactly N*128/4 threads
    reinterpret_cast<float4*>(ptr)[i] = make_float4(0.f, 0.f, 0.f, 0.f);
}
__global__ void k_zero_cnt() {
    int i = blockIdx.x * blockDim.x + threadIdx.x;
    if (i < NNODES) g_cnt[i] = 0;
}
__global__ void k_count(const int* __restrict__ dst) {
    int e = blockIdx.x * blockDim.x + threadIdx.x;          // exactly NEDGES threads
    atomicAdd(&g_cnt[dst[e]], 1);
}
__global__ void k_inv() {
    int i = blockIdx.x * blockDim.x + threadIdx.x;
    if (i < NNODES) g_inv[i] = 1.0f / fmaxf((float)g_cnt[i], 1.0f);
}

// ---------------- node GEMM: C = act( [A1 | A2*rowscale] @ W + bias ) ----------------
// W row-major [(K1+K2) x 128]. 64-node x 128-col tile, 256 threads,
// thread tile = 4 nodes x 8 cols (4 packed f32x2 pairs).
__global__ void __launch_bounds__(256)
k_gemm(const float* __restrict__ A1, int K1,
       const float* __restrict__ A2, int K2, int scaleA2,
       const float* __restrict__ W, const float* __restrict__ bias,
       float* __restrict__ C, int doRelu)
{
    __shared__ float Ash[32][65];                    // padded: conflict-free transpose
    __shared__ unsigned long long Wshp[32][64];      // W as f32x2 pairs

    const int tid  = threadIdx.x;
    const int cg   = tid & 15;          // col group -> cols [8cg, 8cg+8)
    const int rg   = tid >> 4;          // row group -> rows [4rg, 4rg+4)
    const int col0 = cg << 3;
    const int row0 = rg << 2;
    const int n0   = blockIdx.x * 64;
    const int Ktot = K1 + K2;

    unsigned long long acc[4][4];
    #pragma unroll
    for (int i = 0; i < 4; ++i)
        #pragma unroll
        for (int t = 0; t < 4; ++t) acc[i][t] = 0ull;

    for (int kb = 0; kb < Ktot; kb += 32) {
        // stage A (transposed) -- 2048 floats
        #pragma unroll
        for (int l = 0; l < 8; ++l) {
            int e  = tid + l * 256;
            int nd = e >> 5, k = e & 31;
            int gn = n0 + nd, gk = kb + k;
            float v = 0.f;
            if (gn < NNODES) {
                if (gk < K1) v = A1[(size_t)gn * K1 + gk];
                else {
                    v = A2[(size_t)gn * K2 + (gk - K1)];
                    if (scaleA2) v *= g_inv[gn];
                }
            }
            Ash[k][nd] = v;
        }
        // stage W as packed pairs -- 2048 u64
        #pragma unroll
        for (int l = 0; l < 8; ++l) {
            int e = tid + l * 256;
            int k = e >> 6, cp = e & 63;
            Wshp[k][cp] =
                reinterpret_cast<const unsigned long long*>(W + (size_t)(kb + k) * 128)[cp];
        }
        __syncthreads();

        #pragma unroll
        for (int k = 0; k < 32; ++k) {
            float a0 = Ash[k][row0 + 0];
            float a1 = Ash[k][row0 + 1];
            float a2 = Ash[k][row0 + 2];
            float a3 = Ash[k][row0 + 3];
            unsigned long long p0 = pack2(a0, a0);
            unsigned long long p1 = pack2(a1, a1);
            unsigned long long p2 = pack2(a2, a2);
            unsigned long long p3 = pack2(a3, a3);
            ulonglong2 w0 = *reinterpret_cast<const ulonglong2*>(&Wshp[k][cg * 4]);
            ulonglong2 w1 = *reinterpret_cast<const ulonglong2*>(&Wshp[k][cg * 4 + 2]);
            acc[0][0] = fma2(p0, w0.x, acc[0][0]); acc[0][1] = fma2(p0, w0.y, acc[0][1]);
            acc[0][2] = fma2(p0, w1.x, acc[0][2]); acc[0][3] = fma2(p0, w1.y, acc[0][3]);
            acc[1][0] = fma2(p1, w0.x, acc[1][0]); acc[1][1] = fma2(p1, w0.y, acc[1][1]);
            acc[1][2] = fma2(p1, w1.x, acc[1][2]); acc[1][3] = fma2(p1, w1.y, acc[1][3]);
            acc[2][0] = fma2(p2, w0.x, acc[2][0]); acc[2][1] = fma2(p2, w0.y, acc[2][1]);
            acc[2][2] = fma2(p2, w1.x, acc[2][2]); acc[2][3] = fma2(p2, w1.y, acc[2][3]);
            acc[3][0] = fma2(p3, w0.x, acc[3][0]); acc[3][1] = fma2(p3, w0.y, acc[3][1]);
            acc[3][2] = fma2(p3, w1.x, acc[3][2]); acc[3][3] = fma2(p3, w1.y, acc[3][3]);
        }
        __syncthreads();
    }

    float bv[8];
    #pragma unroll
    for (int t = 0; t < 8; ++t) bv[t] = bias ? bias[col0 + t] : 0.f;

    #pragma unroll
    for (int i = 0; i < 4; ++i) {
        int gn = n0 + row0 + i;
        if (gn >= NNODES) continue;
        float2 v0 = unpack2(acc[i][0]);
        float2 v1 = unpack2(acc[i][1]);
        float2 v2 = unpack2(acc[i][2]);
        float2 v3 = unpack2(acc[i][3]);
        float o[8] = { v0.x + bv[0], v0.y + bv[1], v1.x + bv[2], v1.y + bv[3],
                       v2.x + bv[4], v2.y + bv[5], v3.x + bv[6], v3.y + bv[7] };
        if (doRelu) {
            #pragma unroll
            for (int t = 0; t < 8; ++t) o[t] = fmaxf(o[t], 0.f);
        }
        float* cp = &C[(size_t)gn * 128 + col0];
        *reinterpret_cast<float4*>(cp)     = make_float4(o[0], o[1], o[2], o[3]);
        *reinterpret_cast<float4*>(cp + 4) = make_float4(o[4], o[5], o[6], o[7]);
    }
}

// ---------------- edge message + mean-aggregate ----------------
// per edge: m = relu(u[src] + e @ We), red-add into s[dst].  4 edges / warp.
__global__ void __launch_bounds__(256)
k_edge(const float* __restrict__ efeats, const int* __restrict__ src,
       const int* __restrict__ dst, const float* __restrict__ We,
       const float* __restrict__ u, float* __restrict__ s)
{
    __shared__ unsigned long long WeP[32][64];         // We pre-packed as f32x2
    __shared__ unsigned long long Esh[8][4][32];       // [warp][edge][k] duplicated-pair e

    const int tid = threadIdx.x;
    #pragma unroll
    for (int l = 0; l < 8; ++l) {
        int e = tid + l * 256;
        int k = e >> 6, cp = e & 63;
        WeP[k][cp] =
            reinterpret_cast<const unsigned long long*>(We + (size_t)k * 128)[cp];
    }
    __syncthreads();

    const int wid  = tid >> 5;
    const int lane = tid & 31;
    const int eb   = (blockIdx.x * 8 + wid) * 4;       // exact: E = 50000*32

    #pragma unroll
    for (int r = 0; r < 4; ++r) {
        float ev = efeats[(size_t)(eb + r) * 32 + lane];
        Esh[wid][r][lane] = pack2(ev, ev);
    }
    __syncwarp();

    unsigned long long acc[4][2];
    #pragma unroll
    for (int r = 0; r < 4; ++r) { acc[r][0] = 0ull; acc[r][1] = 0ull; }

    #pragma unroll
    for (int k = 0; k < 32; ++k) {
        ulonglong2 w = *reinterpret_cast<const ulonglong2*>(&WeP[k][lane * 2]);
        #pragma unroll
        for (int r = 0; r < 4; ++r) {
            unsigned long long a = Esh[wid][r][k];     // warp broadcast
            acc[r][0] = fma2(a, w.x, acc[r][0]);
            acc[r][1] = fma2(a, w.y, acc[r][1]);
        }
    }

    #pragma unroll
    for (int r = 0; r < 4; ++r) {
        int e  = eb + r;
        int sn = src[e];
        int dn = dst[e];
        float4 uu = *reinterpret_cast<const float4*>(&u[(size_t)sn * 128 + lane * 4]);
        float2 a0 = unpack2(acc[r][0]);
        float2 a1 = unpack2(acc[r][1]);
        float m0 = fmaxf(uu.x + a0.x, 0.f);
        float m1 = fmaxf(uu.y + a0.y, 0.f);
        float m2 = fmaxf(uu.z + a1.x, 0.f);
        float m3 = fmaxf(uu.w + a1.y, 0.f);
        float* sp = &s[(size_t)dn * 128 + lane * 4];
        asm volatile("red.global.add.v4.f32 [%0], {%1, %2, %3, %4};"
                     :: "l"(sp), "f"(m0), "f"(m1), "f"(m2), "f"(m3) : "memory");
    }
}

// ---------------- edge predictor ----------------
// score = relu(p[src] + q[dst]) @ W2 + b2, one warp per edge.
__global__ void __launch_bounds__(256)
k_pred(const int* __restrict__ src, const int* __restrict__ dst,
       const float* __restrict__ p, const float* __restrict__ q,
       const float* __restrict__ W2, const float* __restrict__ b2,
       float* __restrict__ out)
{
    const int wid  = threadIdx.x >> 5;
    const int lane = threadIdx.x & 31;
    const int e    = blockIdx.x * 8 + wid;             // exact: E = 200000*8

    float2 w2[4];
    #pragma unroll
    for (int t = 0; t < 4; ++t)
        w2[t] = reinterpret_cast<const float2*>(W2)[lane * 4 + t];

    int sn = src[e];
    int dn = dst[e];
    float4 pp = *reinterpret_cast<const float4*>(&p[(size_t)sn * 128 + lane * 4]);
    float4 qq = *reinterpret_cast<const float4*>(&q[(size_t)dn * 128 + lane * 4]);
    float h0 = fmaxf(pp.x + qq.x, 0.f);
    float h1 = fmaxf(pp.y + qq.y, 0.f);
    float h2 = fmaxf(pp.z + qq.z, 0.f);
    float h3 = fmaxf(pp.w + qq.w, 0.f);
    float s0 = h0 * w2[0].x + h1 * w2[1].x + h2 * w2[2].x + h3 * w2[3].x;
    float s1 = h0 * w2[0].y + h1 * w2[1].y + h2 * w2[2].y + h3 * w2[3].y;

    #pragma unroll
    for (int off = 16; off > 0; off >>= 1) {
        s0 += __shfl_xor_sync(0xffffffffu, s0, off);
        s1 += __shfl_xor_sync(0xffffffffu, s1, off);
    }
    if (lane == 0) {
        out[2 * (size_t)e]     = s0 + b2[0];
        out[2 * (size_t)e + 1] = s1 + b2[1];
    }
}

// ---------------- launch ----------------
extern "C" void kernel_launch(void* const* d_in, const int* in_sizes, int n_in,
                              void* d_out, int out_size)
{
    const float* nfeats = (const float*)d_in[0];
    const float* efeats = (const float*)d_in[1];
    const int*   src    = (const int*)  d_in[2];
    const int*   dst    = (const int*)  d_in[3];
    const float* Wm1 = (const float*)d_in[4];  const float* bm1 = (const float*)d_in[5];
    const float* Wa1 = (const float*)d_in[6];  const float* ba1 = (const float*)d_in[7];
    const float* Wm2 = (const float*)d_in[8];  const float* bm2 = (const float*)d_in[9];
    const float* Wa2 = (const float*)d_in[10]; const float* ba2 = (const float*)d_in[11];
    const float* W1  = (const float*)d_in[12]; const float* b1  = (const float*)d_in[13];
    const float* W2  = (const float*)d_in[14]; const float* b2  = (const float*)d_in[15];
    float* out = (float*)d_out;

    float *u, *s, *h1, *h2, *p, *q;
    cudaGetSymbolAddress((void**)&u,  g_u);
    cudaGetSymbolAddress((void**)&s,  g_s);
    cudaGetSymbolAddress((void**)&h1, g_h1);
    cudaGetSymbolAddress((void**)&h2, g_h2);
    cudaGetSymbolAddress((void**)&p,  g_p);
    cudaGetSymbolAddress((void**)&q,  g_q);

    const int GB = (NNODES + 63) / 64;        // 782 gemm blocks
    const int ZB = NNODES * 128 / 4 / 256;    // 6250 zero blocks (exact)
    const int EB = NEDGES / 32;               // 50000 edge blocks (exact)
    const int CB = NEDGES / 256;              // 6250 count blocks (exact)
    const int NB = (NNODES + 255) / 256;      // 196

    // degree counts (once)
    k_zero_cnt<<<NB, 256>>>();
    k_count<<<CB, 256>>>(dst);
    k_inv<<<NB, 256>>>();

    // ---- SAGE layer 1 ----
    k_zero_f4<<<ZB, 256>>>(s);
    k_gemm<<<GB, 256>>>(nfeats, 64, nullptr, 0, 0, Wm1, bm1, u, 0);
    k_edge<<<EB, 256>>>(efeats, src, dst, Wm1 + 64 * 128, u, s);
    k_gemm<<<GB, 256>>>(nfeats, 64, s, 128, 1, Wa1, ba1, h1, 1);

    // ---- SAGE layer 2 ----
    k_zero_f4<<<ZB, 256>>>(s);
    k_gemm<<<GB, 256>>>(h1, 128, nullptr, 0, 0, Wm2, bm2, u, 0);
    k_edge<<<EB, 256>>>(efeats, src, dst, Wm2 + 128 * 128, u, s);
    k_gemm<<<GB, 256>>>(h1, 128, s, 128, 1, Wa2, ba2, h2, 1);

    // ---- predictor ----
    k_gemm<<<GB, 256>>>(h2, 128, nullptr, 0, 0, W1, b1, p, 0);
    k_gemm<<<GB, 256>>>(h2, 128, nullptr, 0, 0, W1 + 128 * 128, nullptr, q, 0);
    k_pred<<<NEDGES / 8, 256>>>(src, dst, p, q, W2, b2, out);
}